// round 15
// baseline (speedup 1.0000x reference)
#include <cuda_runtime.h>
#include <cuda_fp16.h>
#include <cstdint>

#define BATCH 4
#define SEQ   2048
#define EMB   1024
#define NH    16
#define HD    64
#define E3    (3*EMB)
#define MROWS (BATCH*SEQ)

// ---------------- scratch (static device allocations) ----------------
__device__ __half g_qkv[(size_t)MROWS * E3];
__device__ __half g_ctx[(size_t)MROWS * EMB];
__device__ __half g_xh [(size_t)MROWS * EMB];
__device__ __half g_w1h[(size_t)E3   * EMB];
__device__ __half g_w2h[(size_t)EMB  * EMB];
__device__ float  g_bias[2*SEQ - 1];      // pre-scaled by log2(e)
__device__ int    g_maxd;                 // max_rel_dist (runtime)

#define QSCALE 0.180336879f               // 0.125 * log2(e)

// ---------------- helpers ----------------
__device__ __forceinline__ void mma_f16(float c[4], const uint32_t a[4],
                                        uint32_t b0, uint32_t b1) {
    asm volatile(
        "mma.sync.aligned.m16n8k16.row.col.f32.f16.f16.f32 "
        "{%0,%1,%2,%3}, {%4,%5,%6,%7}, {%8,%9}, {%0,%1,%2,%3};"
        : "+f"(c[0]), "+f"(c[1]), "+f"(c[2]), "+f"(c[3])
        : "r"(a[0]), "r"(a[1]), "r"(a[2]), "r"(a[3]), "r"(b0), "r"(b1));
}

__device__ __forceinline__ void ldsm_x4(uint32_t* r, uint32_t addr) {
    asm volatile("ldmatrix.sync.aligned.m8n8.x4.shared.b16 {%0,%1,%2,%3}, [%4];"
                 : "=r"(r[0]), "=r"(r[1]), "=r"(r[2]), "=r"(r[3]) : "r"(addr));
}
__device__ __forceinline__ void ldsm_x4_t(uint32_t* r, uint32_t addr) {
    asm volatile("ldmatrix.sync.aligned.m8n8.x4.trans.shared.b16 {%0,%1,%2,%3}, [%4];"
                 : "=r"(r[0]), "=r"(r[1]), "=r"(r[2]), "=r"(r[3]) : "r"(addr));
}
__device__ __forceinline__ void ldsm_x2_t(uint32_t* r, uint32_t addr) {
    asm volatile("ldmatrix.sync.aligned.m8n8.x2.trans.shared.b16 {%0,%1}, [%2];"
                 : "=r"(r[0]), "=r"(r[1]) : "r"(addr));
}

__device__ __forceinline__ void cp16(void* dst_smem, const void* src) {
    uint32_t d = (uint32_t)__cvta_generic_to_shared(dst_smem);
    asm volatile("cp.async.cg.shared.global [%0], [%1], 16;\n"
                 :: "r"(d), "l"(src));
}
#define CP_COMMIT()  asm volatile("cp.async.commit_group;\n" ::: "memory")
#define CP_WAIT(n)   asm volatile("cp.async.wait_group %0;\n" :: "n"(n) : "memory")

__device__ __forceinline__ uint32_t smem_u32(const void* p) {
    return (uint32_t)__cvta_generic_to_shared(p);
}

__device__ __forceinline__ uint32_t packh2(float a, float b) {
    __half2 h = __floats2half2_rn(a, b);
    return *(uint32_t*)&h;
}

// ---------------- prep kernels ----------------
__global__ void prep_bias_kernel(const float* __restrict__ rel_bias,
                                 const int* __restrict__ p_maxd)
{
    __shared__ float b1d[512];
    int M = *p_maxd;
    if (threadIdx.x == 0) g_maxd = M;
    int n = 2*M + 1;
    if (n > 512) n = 512;
    for (int r = threadIdx.x; r < n; r += blockDim.x) {
        float s = 0.f;
        #pragma unroll
        for (int h = 0; h < NH; h++) s += rel_bias[r*NH + h];
        b1d[r] = s * (1.0f / NH) * 1.44269504f;   // log2(e) folded in
    }
    __syncthreads();
    for (int t = threadIdx.x; t < 2*SEQ - 1; t += blockDim.x) {
        int d = t - (SEQ - 1);
        d = max(-M, min(M, d));
        g_bias[t] = b1d[d + M];
    }
}

// one launch converts x, w1, w2 (segments by block range)
__global__ void to_half3_kernel(const float* __restrict__ s0, __half* __restrict__ d0, int n0,
                                const float* __restrict__ s1, __half* __restrict__ d1, int n1,
                                const float* __restrict__ s2, __half* __restrict__ d2, int n2)
{
    int i = blockIdx.x * blockDim.x + threadIdx.x;
    const float* src; __half* dst; int n;
    if (i < n0)                { src = s0; dst = d0; n = n0; }
    else if (i < n0 + n1)      { src = s1; dst = d1; n = n1; i -= n0; }
    else                       { src = s2; dst = d2; n = n2; i -= n0 + n1; }
    if (i < n) {
        float4 v = ((const float4*)src)[i];
        __half2 h0 = __floats2half2_rn(v.x, v.y);
        __half2 h1 = __floats2half2_rn(v.z, v.w);
        uint2 u;
        u.x = *(uint32_t*)&h0;
        u.y = *(uint32_t*)&h1;
        *(uint2*)(dst + (size_t)i*4) = u;
    }
}

// ---------------- FP16 TC GEMM: C = A @ W^T + bias (unchanged R14) ---------
#define GSW   72
#define GSTGH (2*128*GSW)           // halfs per stage (36864 B)
__global__ void __launch_bounds__(128, 3) gemm_f16_kernel(
    const __half* __restrict__ A, const __half* __restrict__ W,
    const float* __restrict__ bias, void* __restrict__ Cout,
    int M, int N, int K, int halfOut, int qcols, float qscale)
{
    extern __shared__ __half smh[];

    const int tid  = threadIdx.x;
    const int lane = tid & 31;
    const int warp = tid >> 5;
    const int g    = lane >> 2;
    const int t4   = lane & 3;
    const int wm   = (warp & 1) * 64;
    const int wn   = (warp >> 1) * 64;
    const int m0   = blockIdx.y * 128;
    const int n0   = blockIdx.x * 128;
    const int KT   = K >> 6;

    const int sel = lane >> 3, sub = lane & 7;
    const uint32_t ax_off = (uint32_t)(((((sel & 1)*8 + sub)*GSW) + (sel >> 1)*8) * 2);
    const uint32_t bx_off = (uint32_t)(((((sel >> 1)*8 + sub)*GSW) + (sel & 1)*8) * 2);

    float acc[4][8][4] = {};

    auto issue = [&](int it) {
        __half* as_ = smh + (it & 1) * GSTGH;
        __half* bs_ = as_ + 128*GSW;
        const __half* ap = A + (size_t)m0*K + it*64;
        const __half* wp = W + (size_t)n0*K + it*64;
        #pragma unroll
        for (int i = 0; i < 8; i++) {
            int gi = tid + i*128;
            int row = gi >> 3, c8 = (gi & 7) * 8;
            cp16(&as_[row*GSW + c8], ap + (size_t)row*K + c8);
            cp16(&bs_[row*GSW + c8], wp + (size_t)row*K + c8);
        }
    };

    issue(0); CP_COMMIT();

    for (int it = 0; it < KT; it++) {
        CP_WAIT(0);
        __syncthreads();
        if (it + 1 < KT) { issue(it + 1); CP_COMMIT(); }

        const uint32_t as_u = smem_u32(smh + (it & 1) * GSTGH);
        const uint32_t bs_u = as_u + 128*GSW*2;

        #pragma unroll
        for (int ks = 0; ks < 4; ks++) {
            uint32_t af[4][4], bf[4][4];
            #pragma unroll
            for (int mt = 0; mt < 4; mt++)
                ldsm_x4(af[mt], as_u + (uint32_t)((((wm + mt*16)*GSW) + ks*16) * 2) + ax_off);
            #pragma unroll
            for (int p = 0; p < 4; p++)
                ldsm_x4(bf[p], bs_u + (uint32_t)((((wn + p*16)*GSW) + ks*16) * 2) + bx_off);
            #pragma unroll
            for (int mt = 0; mt < 4; mt++)
                #pragma unroll
                for (int nt = 0; nt < 8; nt++)
                    mma_f16(acc[mt][nt], af[mt],
                            bf[nt >> 1][(nt & 1)*2], bf[nt >> 1][(nt & 1)*2 + 1]);
        }
    }

    #pragma unroll
    for (int mt = 0; mt < 4; mt++) {
        int m = m0 + wm + mt*16 + g;
        #pragma unroll
        for (int nt = 0; nt < 8; nt++) {
            int n = n0 + wn + nt*8 + 2*t4;
            float2 bv = *(const float2*)(bias + n);
            float o00 = acc[mt][nt][0] + bv.x, o01 = acc[mt][nt][1] + bv.y;
            float o10 = acc[mt][nt][2] + bv.x, o11 = acc[mt][nt][3] + bv.y;
            if (halfOut) {
                float sc = (n < qcols) ? qscale : 1.0f;
                o00 *= sc; o01 *= sc; o10 *= sc; o11 *= sc;
                __half* C = (__half*)Cout;
                *(__half2*)(C + (size_t)m*N + n)       = __floats2half2_rn(o00, o01);
                *(__half2*)(C + (size_t)(m + 8)*N + n) = __floats2half2_rn(o10, o11);
            } else {
                float* C = (float*)Cout;
                *(float2*)(C + (size_t)m*N + n)       = make_float2(o00, o01);
                *(float2*)(C + (size_t)(m + 8)*N + n) = make_float2(o10, o11);
            }
        }
    }
}

// ---------------- FP16 TC flash attention (j-fused pipeline) ---------------
// Grid (SEQ/128, BATCH*NH), 128 threads (4 warps), warp = 32 q-rows.
// Per kv-chunk j: S-mma(j) -> bias(j) -> exp2(j) -> PV-mma(j). Live score
// state drops from 96 to 32 regs -> 3 CTAs/SM; softmax(j) overlaps
// S-mma(j+1). 2-stage KV ring. Row sums via ones-column mma.
#define ASW 72
#define VSW 80
#define AKV (64*ASW + 64*VSW)      // halfs per kv stage (9728)
#define SOFT_C 4.0f
__global__ void __launch_bounds__(128, 3) attn_f16_kernel(
    const __half* __restrict__ qkv, __half* __restrict__ ctx)
{
    extern __shared__ __half sma[];
    __half* q_s = sma;                 // 128*72 halfs

    const int tid  = threadIdx.x;
    const int lane = tid & 31;
    const int warp = tid >> 5;
    const int g    = lane >> 2;
    const int t4   = lane & 3;
    const int bh = blockIdx.y;
    const int b  = bh >> 4;
    const int h  = bh & 15;
    const int q0 = blockIdx.x * 128;
    const int wr = warp * 32;          // warp's q-row base (2 m-tiles)

    const int sel = lane >> 3, sub = lane & 7;
    const uint32_t ax_off = (uint32_t)(((((sel & 1)*8 + sub)*ASW) + (sel >> 1)*8) * 2);
    const uint32_t bx_off = (uint32_t)(((((sel >> 1)*8 + sub)*ASW) + (sel & 1)*8) * 2);
    const uint32_t av_off = (uint32_t)(((((sel & 1)*8 + sub)*VSW) + (sel >> 1)*8) * 2);
    const uint32_t q_u = smem_u32(q_s);

    // bias flat-tile constants (runtime M)
    const int Mrd = g_maxd;
    const float bias_hi = g_bias[2*SEQ - 2];
    const float bias_lo = g_bias[0];
    const int hiThresh = q0 - 63 - Mrd;
    const int loThresh = q0 + 127 + Mrd;

    auto kv_issue = [&](int t) {
        __half* ks_ = sma + 128*ASW + (t & 1) * AKV;
        __half* vs_ = ks_ + 64*ASW;
        const __half* kg = qkv + ((size_t)(b*SEQ + t*64))*E3 + EMB + h*HD;
        const __half* vg = kg + EMB;
        #pragma unroll
        for (int i = 0; i < 4; i++) {
            int gi = tid + i*128;
            int row = gi >> 3, c8 = (gi & 7) * 8;
            cp16(&ks_[row*ASW + c8], kg + (size_t)row*E3 + c8);
            cp16(&vs_[row*VSW + c8], vg + (size_t)row*E3 + c8);
        }
    };

    kv_issue(0); CP_COMMIT();

    // stage Q (pre-scaled by GEMM1 epilogue) - plain 16B copies
    {
        const __half* qg = qkv + ((size_t)(b*SEQ + q0))*E3 + h*HD;
        const __half* qrow = qg + (size_t)tid*E3;
        #pragma unroll
        for (int gr = 0; gr < 9; gr++)
            *(uint4*)&q_s[tid*ASW + gr*8] = *(const uint4*)(qrow + gr*8);
    }

    // ones columns for both v stage buffers (cols 64..71: {1,0,...})
    if (tid < 64) {
        uint4 w;
        w.x = packh2(1.0f, 0.0f);
        w.y = 0u; w.z = 0u; w.w = 0u;
        #pragma unroll
        for (int sbuf = 0; sbuf < 2; sbuf++) {
            __half* vs = sma + 128*ASW + sbuf*AKV + 64*ASW;
            *(uint4*)&vs[tid*VSW + 64] = w;
        }
    }
    __syncthreads();

    // hoist loop-invariant Q fragments into registers
    const uint32_t qwb = (uint32_t)(wr*ASW*2);
    uint32_t aqr[2][4][4];
    #pragma unroll
    for (int ks = 0; ks < 4; ks++) {
        ldsm_x4(aqr[0][ks], q_u + qwb + (uint32_t)(ks*16*2)            + ax_off);
        ldsm_x4(aqr[1][ks], q_u + qwb + (uint32_t)((16*ASW + ks*16)*2) + ax_off);
    }

    float oacc[2][8][4] = {};
    float oaccS[2][4] = {};            // ones-column sums (col 64 -> c0/c2)

    const int KT = SEQ/64;
    for (int t = 0; t < KT; t++) {
        CP_WAIT(0);
        __syncthreads();
        if (t + 1 < KT) { kv_issue(t + 1); CP_COMMIT(); }

        const uint32_t k_u = smem_u32(sma + 128*ASW + (t & 1) * AKV);
        const uint32_t v_u = k_u + 64*ASW*2;
        const int kt = t * 64;

        float cb = 0.f;
        bool flat = true;
        if (kt <= hiThresh)      cb = bias_hi;
        else if (kt >= loThresh) cb = bias_lo;
        else                     flat = false;
        const __half2 sh = __float2half2_rn(SOFT_C - cb);

        // ---- per kv-chunk j: S -> bias -> exp2 -> PV ----
        #pragma unroll
        for (int p = 0; p < 4; p++) {
            // S(j): 16 q-cols x 16 kv-rows per mma; accumulate over d (ks)
            float s[2][2][4] = {};
            #pragma unroll
            for (int ks = 0; ks < 4; ks++) {
                uint32_t bk[4];
                ldsm_x4(bk, k_u + (uint32_t)(((p*16)*ASW + ks*16) * 2) + bx_off);
                #pragma unroll
                for (int mt = 0; mt < 2; mt++) {
                    mma_f16(s[mt][0], aqr[mt][ks], bk[0], bk[1]);
                    mma_f16(s[mt][1], aqr[mt][ks], bk[2], bk[3]);
                }
            }

            // bias(j): exact gather only near the diagonal
            if (!flat) {
                #pragma unroll
                for (int mt = 0; mt < 2; mt++) {
                    int qr = q0 + wr + mt*16 + g;
                    #pragma unroll
                    for (int ntl = 0; ntl < 2; ntl++) {
                        int kcol = kt + (2*p + ntl)*8 + 2*t4;
                        int idx0 = qr - kcol + (SEQ - 1);
                        s[mt][ntl][0] += __ldg(&g_bias[idx0]);
                        s[mt][ntl][1] += __ldg(&g_bias[idx0 - 1]);
                        s[mt][ntl][2] += __ldg(&g_bias[idx0 + 8]);
                        s[mt][ntl][3] += __ldg(&g_bias[idx0 + 7]);
                    }
                }
            }

            // softmax(j): p = exp2(s + cb - C); outputs ARE PV A-fragments
            uint32_t ap[2][4];
            #pragma unroll
            for (int mt = 0; mt < 2; mt++) {
                __half2 h00; { uint32_t u = packh2(s[mt][0][0], s[mt][0][1]); h00 = *(__half2*)&u; }
                __half2 h01; { uint32_t u = packh2(s[mt][0][2], s[mt][0][3]); h01 = *(__half2*)&u; }
                __half2 h10; { uint32_t u = packh2(s[mt][1][0], s[mt][1][1]); h10 = *(__half2*)&u; }
                __half2 h11; { uint32_t u = packh2(s[mt][1][2], s[mt][1][3]); h11 = *(__half2*)&u; }
                __half2 e00 = h2exp2(__hsub2(h00, sh));
                __half2 e01 = h2exp2(__hsub2(h01, sh));
                __half2 e10 = h2exp2(__hsub2(h10, sh));
                __half2 e11 = h2exp2(__hsub2(h11, sh));
                ap[mt][0] = *(uint32_t*)&e00;
                ap[mt][1] = *(uint32_t*)&e01;
                ap[mt][2] = *(uint32_t*)&e10;
                ap[mt][3] = *(uint32_t*)&e11;
            }

            // PV(j): O += P_j @ V_j ; ones-column accumulates row sums
            #pragma unroll
            for (int pout = 0; pout < 4; pout++) {
                uint32_t bv[4];
                ldsm_x4_t(bv, v_u + (uint32_t)(((p*16)*VSW + pout*16) * 2) + av_off);
                #pragma unroll
                for (int mt = 0; mt < 2; mt++) {
                    mma_f16(oacc[mt][2*pout],     ap[mt], bv[0], bv[1]);
                    mma_f16(oacc[mt][2*pout + 1], ap[mt], bv[2], bv[3]);
                }
            }
            uint32_t bs2[2];
            ldsm_x2_t(bs2, v_u + (uint32_t)(((p*16)*VSW + 64) * 2) + av_off);
            #pragma unroll
            for (int mt = 0; mt < 2; mt++)
                mma_f16(oaccS[mt], ap[mt], bs2[0], bs2[1]);
        }
    }

    // epilogue: broadcast row sums (held in t4==0 quads), normalize, store
    #pragma unroll
    for (int mt = 0; mt < 2; mt++) {
        float l0 = __shfl_sync(0xffffffffu, oaccS[mt][0], lane & 0x1c);
        float l1 = __shfl_sync(0xffffffffu, oaccS[mt][2], lane & 0x1c);
        float inv0 = 1.0f / l0;
        float inv1 = 1.0f / l1;
        __half* og = ctx + ((size_t)(b*SEQ + q0 + wr + mt*16 + g))*EMB + h*HD;
        #pragma unroll
        for (int nt = 0; nt < 8; nt++) {
            int d = nt*8 + 2*t4;
            *(__half2*)(og + d) = __floats2half2_rn(oacc[mt][nt][0]*inv0, oacc[mt][nt][1]*inv0);
            *(__half2*)(og + (size_t)8*EMB + d) = __floats2half2_rn(oacc[mt][nt][2]*inv1, oacc[mt][nt][3]*inv1);
        }
    }
}

// ---------------- launch ----------------
extern "C" void kernel_launch(void* const* d_in, const int* in_sizes, int n_in,
                              void* d_out, int out_size)
{
    const float* x   = (const float*)d_in[0];
    const float* w1  = (const float*)d_in[1];
    const float* b1  = (const float*)d_in[2];
    const float* w2  = (const float*)d_in[3];
    const float* b2  = (const float*)d_in[4];
    const float* rb  = (const float*)d_in[5];
    const int*   md  = (const int*)d_in[6];
    float* out = (float*)d_out;

    __half *qkv, *ctxp, *xh, *w1h, *w2h;
    cudaGetSymbolAddress((void**)&qkv,  g_qkv);
    cudaGetSymbolAddress((void**)&ctxp, g_ctx);
    cudaGetSymbolAddress((void**)&xh,   g_xh);
    cudaGetSymbolAddress((void**)&w1h,  g_w1h);
    cudaGetSymbolAddress((void**)&w2h,  g_w2h);

    const int gemm_smem = 2 * GSTGH * (int)sizeof(__half);              // 73728 B
    const int attn_smem = (128*ASW + 2*AKV) * (int)sizeof(__half);      // 57344 B
    cudaFuncSetAttribute(gemm_f16_kernel,
                         cudaFuncAttributeMaxDynamicSharedMemorySize, gemm_smem);
    cudaFuncSetAttribute(attn_f16_kernel,
                         cudaFuncAttributeMaxDynamicSharedMemorySize, attn_smem);

    prep_bias_kernel<<<1, 256>>>(rb, md);

    int n4x  = MROWS*EMB/4, n4w1 = E3*EMB/4, n4w2 = EMB*EMB/4;
    int n4all = n4x + n4w1 + n4w2;
    to_half3_kernel<<<(n4all + 255)/256, 256>>>(x, xh, n4x, w1, w1h, n4w1, w2, w2h, n4w2);

    dim3 g1(E3/128, MROWS/128);       // (24, 64)
    gemm_f16_kernel<<<g1, 128, gemm_smem>>>(xh, w1h, b1, qkv, MROWS, E3, EMB,
                                            1, EMB, QSCALE);

    dim3 ga(SEQ/128, BATCH*NH);       // (16, 64)
    attn_f16_kernel<<<ga, 128, attn_smem>>>(qkv, ctxp);

    dim3 g2(EMB/128, MROWS/128);      // (8, 64)
    gemm_f16_kernel<<<g2, 128, gemm_smem>>>(ctxp, w2h, b2, out, MROWS, EMB, EMB,
                                            0, 0, 1.0f);
}

// round 16
// speedup vs baseline: 1.0278x; 1.0278x over previous
#include <cuda_runtime.h>
#include <cuda_fp16.h>
#include <cstdint>

#define BATCH 4
#define SEQ   2048
#define EMB   1024
#define NH    16
#define HD    64
#define E3    (3*EMB)
#define MROWS (BATCH*SEQ)

// ---------------- scratch (static device allocations) ----------------
__device__ __half g_qkv[(size_t)MROWS * E3];
__device__ __half g_ctx[(size_t)MROWS * EMB];
__device__ __half g_xh [(size_t)MROWS * EMB];
__device__ __half g_w1h[(size_t)E3   * EMB];
__device__ __half g_w2h[(size_t)EMB  * EMB];
__device__ float  g_bias[2*SEQ - 1];      // pre-scaled by log2(e)
__device__ int    g_maxd;                 // max_rel_dist (runtime)

#define QSCALE 0.180336879f               // 0.125 * log2(e)

// ---------------- helpers ----------------
__device__ __forceinline__ void mma_f16(float c[4], const uint32_t a[4],
                                        uint32_t b0, uint32_t b1) {
    asm volatile(
        "mma.sync.aligned.m16n8k16.row.col.f32.f16.f16.f32 "
        "{%0,%1,%2,%3}, {%4,%5,%6,%7}, {%8,%9}, {%0,%1,%2,%3};"
        : "+f"(c[0]), "+f"(c[1]), "+f"(c[2]), "+f"(c[3])
        : "r"(a[0]), "r"(a[1]), "r"(a[2]), "r"(a[3]), "r"(b0), "r"(b1));
}

__device__ __forceinline__ void ldsm_x4(uint32_t* r, uint32_t addr) {
    asm volatile("ldmatrix.sync.aligned.m8n8.x4.shared.b16 {%0,%1,%2,%3}, [%4];"
                 : "=r"(r[0]), "=r"(r[1]), "=r"(r[2]), "=r"(r[3]) : "r"(addr));
}
__device__ __forceinline__ void ldsm_x4_t(uint32_t* r, uint32_t addr) {
    asm volatile("ldmatrix.sync.aligned.m8n8.x4.trans.shared.b16 {%0,%1,%2,%3}, [%4];"
                 : "=r"(r[0]), "=r"(r[1]), "=r"(r[2]), "=r"(r[3]) : "r"(addr));
}
__device__ __forceinline__ void ldsm_x2_t(uint32_t* r, uint32_t addr) {
    asm volatile("ldmatrix.sync.aligned.m8n8.x2.trans.shared.b16 {%0,%1}, [%2];"
                 : "=r"(r[0]), "=r"(r[1]) : "r"(addr));
}

__device__ __forceinline__ void cp16(void* dst_smem, const void* src) {
    uint32_t d = (uint32_t)__cvta_generic_to_shared(dst_smem);
    asm volatile("cp.async.cg.shared.global [%0], [%1], 16;\n"
                 :: "r"(d), "l"(src));
}
#define CP_COMMIT()  asm volatile("cp.async.commit_group;\n" ::: "memory")
#define CP_WAIT(n)   asm volatile("cp.async.wait_group %0;\n" :: "n"(n) : "memory")

__device__ __forceinline__ uint32_t smem_u32(const void* p) {
    return (uint32_t)__cvta_generic_to_shared(p);
}

__device__ __forceinline__ uint32_t packh2(float a, float b) {
    __half2 h = __floats2half2_rn(a, b);
    return *(uint32_t*)&h;
}

// ---------------- unified prep: bias table (block 0) + fp32->fp16 copies ----
__global__ void prep_all_kernel(const float* __restrict__ rel_bias,
                                const int* __restrict__ p_maxd,
                                const float* __restrict__ s0, __half* __restrict__ d0, int n0,
                                const float* __restrict__ s1, __half* __restrict__ d1, int n1,
                                const float* __restrict__ s2, __half* __restrict__ d2, int n2)
{
    if (blockIdx.x == 0) {
        __shared__ float b1d[512];
        int M = *p_maxd;
        if (threadIdx.x == 0) g_maxd = M;
        int n = 2*M + 1;
        if (n > 512) n = 512;
        for (int r = threadIdx.x; r < n; r += blockDim.x) {
            float s = 0.f;
            #pragma unroll
            for (int h = 0; h < NH; h++) s += rel_bias[r*NH + h];
            b1d[r] = s * (1.0f / NH) * 1.44269504f;
        }
        __syncthreads();
        for (int t = threadIdx.x; t < 2*SEQ - 1; t += blockDim.x) {
            int d = t - (SEQ - 1);
            d = max(-M, min(M, d));
            g_bias[t] = b1d[d + M];
        }
        return;
    }
    int i = (blockIdx.x - 1) * blockDim.x + threadIdx.x;
    const float* src; __half* dst; int n;
    if (i < n0)                { src = s0; dst = d0; n = n0; }
    else if (i < n0 + n1)      { src = s1; dst = d1; n = n1; i -= n0; }
    else                       { src = s2; dst = d2; n = n2; i -= n0 + n1; }
    if (i < n) {
        float4 v = ((const float4*)src)[i];
        __half2 h0 = __floats2half2_rn(v.x, v.y);
        __half2 h1 = __floats2half2_rn(v.z, v.w);
        uint2 u;
        u.x = *(uint32_t*)&h0;
        u.y = *(uint32_t*)&h1;
        *(uint2*)(dst + (size_t)i*4) = u;
    }
}

// ---------------- FP16 TC GEMM: C = A @ W^T + bias -------------------------
// Block 128x128x64, 128 thr (4 warps in 2x2), warp tile 64x64.
// 2-stage cp.async, single sync/iter. Optional column-range output scale
// (folds attention's Q pre-scale into the qkv epilogue).
#define GSW   72
#define GSTGH (2*128*GSW)           // halfs per stage (36864 B)
__global__ void __launch_bounds__(128, 3) gemm_f16_kernel(
    const __half* __restrict__ A, const __half* __restrict__ W,
    const float* __restrict__ bias, void* __restrict__ Cout,
    int M, int N, int K, int halfOut, int qcols, float qscale)
{
    extern __shared__ __half smh[];

    const int tid  = threadIdx.x;
    const int lane = tid & 31;
    const int warp = tid >> 5;
    const int g    = lane >> 2;
    const int t4   = lane & 3;
    const int wm   = (warp & 1) * 64;
    const int wn   = (warp >> 1) * 64;
    const int m0   = blockIdx.y * 128;
    const int n0   = blockIdx.x * 128;
    const int KT   = K >> 6;

    const int sel = lane >> 3, sub = lane & 7;
    const uint32_t ax_off = (uint32_t)(((((sel & 1)*8 + sub)*GSW) + (sel >> 1)*8) * 2);
    const uint32_t bx_off = (uint32_t)(((((sel >> 1)*8 + sub)*GSW) + (sel & 1)*8) * 2);

    float acc[4][8][4] = {};

    auto issue = [&](int it) {
        __half* as_ = smh + (it & 1) * GSTGH;
        __half* bs_ = as_ + 128*GSW;
        const __half* ap = A + (size_t)m0*K + it*64;
        const __half* wp = W + (size_t)n0*K + it*64;
        #pragma unroll
        for (int i = 0; i < 8; i++) {
            int gi = tid + i*128;
            int row = gi >> 3, c8 = (gi & 7) * 8;
            cp16(&as_[row*GSW + c8], ap + (size_t)row*K + c8);
            cp16(&bs_[row*GSW + c8], wp + (size_t)row*K + c8);
        }
    };

    issue(0); CP_COMMIT();

    for (int it = 0; it < KT; it++) {
        CP_WAIT(0);
        __syncthreads();
        if (it + 1 < KT) { issue(it + 1); CP_COMMIT(); }

        const uint32_t as_u = smem_u32(smh + (it & 1) * GSTGH);
        const uint32_t bs_u = as_u + 128*GSW*2;

        #pragma unroll
        for (int ks = 0; ks < 4; ks++) {
            uint32_t af[4][4], bf[4][4];
            #pragma unroll
            for (int mt = 0; mt < 4; mt++)
                ldsm_x4(af[mt], as_u + (uint32_t)((((wm + mt*16)*GSW) + ks*16) * 2) + ax_off);
            #pragma unroll
            for (int p = 0; p < 4; p++)
                ldsm_x4(bf[p], bs_u + (uint32_t)((((wn + p*16)*GSW) + ks*16) * 2) + bx_off);
            #pragma unroll
            for (int mt = 0; mt < 4; mt++)
                #pragma unroll
                for (int nt = 0; nt < 8; nt++)
                    mma_f16(acc[mt][nt], af[mt],
                            bf[nt >> 1][(nt & 1)*2], bf[nt >> 1][(nt & 1)*2 + 1]);
        }
    }

    #pragma unroll
    for (int mt = 0; mt < 4; mt++) {
        int m = m0 + wm + mt*16 + g;
        #pragma unroll
        for (int nt = 0; nt < 8; nt++) {
            int n = n0 + wn + nt*8 + 2*t4;
            float2 bv = *(const float2*)(bias + n);
            float o00 = acc[mt][nt][0] + bv.x, o01 = acc[mt][nt][1] + bv.y;
            float o10 = acc[mt][nt][2] + bv.x, o11 = acc[mt][nt][3] + bv.y;
            if (halfOut) {
                float sc = (n < qcols) ? qscale : 1.0f;
                o00 *= sc; o01 *= sc; o10 *= sc; o11 *= sc;
                __half* C = (__half*)Cout;
                *(__half2*)(C + (size_t)m*N + n)       = __floats2half2_rn(o00, o01);
                *(__half2*)(C + (size_t)(m + 8)*N + n) = __floats2half2_rn(o10, o11);
            } else {
                float* C = (float*)Cout;
                *(float2*)(C + (size_t)m*N + n)       = make_float2(o00, o01);
                *(float2*)(C + (size_t)(m + 8)*N + n) = make_float2(o10, o11);
            }
        }
    }
}

// ---------------- FP16 TC flash attention (R13 champion layout) ------------
// Grid (SEQ/128, BATCH*NH), 128 threads (4 warps), warp = 32 q-rows.
// Shift-invariant softmax; row sums via ones-column mma; Q pre-scaled by
// GEMM1 epilogue (plain 16B staging); 2-STAGE KV ring, single sync/iter.
#define ASW 72
#define VSW 80
#define AKV (64*ASW + 64*VSW)      // halfs per kv stage (9728)
#define SOFT_C 4.0f
__global__ void __launch_bounds__(128, 2) attn_f16_kernel(
    const __half* __restrict__ qkv, __half* __restrict__ ctx)
{
    extern __shared__ __half sma[];
    __half* q_s = sma;                 // 128*72 halfs

    const int tid  = threadIdx.x;
    const int lane = tid & 31;
    const int warp = tid >> 5;
    const int g    = lane >> 2;
    const int t4   = lane & 3;
    const int bh = blockIdx.y;
    const int b  = bh >> 4;
    const int h  = bh & 15;
    const int q0 = blockIdx.x * 128;
    const int wr = warp * 32;          // warp's q-row base (2 m-tiles)

    const int sel = lane >> 3, sub = lane & 7;
    const uint32_t ax_off = (uint32_t)(((((sel & 1)*8 + sub)*ASW) + (sel >> 1)*8) * 2);
    const uint32_t bx_off = (uint32_t)(((((sel >> 1)*8 + sub)*ASW) + (sel & 1)*8) * 2);
    const uint32_t av_off = (uint32_t)(((((sel & 1)*8 + sub)*VSW) + (sel >> 1)*8) * 2);
    const uint32_t q_u = smem_u32(q_s);

    // bias flat-tile constants (runtime M)
    const int Mrd = g_maxd;
    const float bias_hi = g_bias[2*SEQ - 2];
    const float bias_lo = g_bias[0];
    const int hiThresh = q0 - 63 - Mrd;
    const int loThresh = q0 + 127 + Mrd;

    auto kv_issue = [&](int t) {
        __half* ks_ = sma + 128*ASW + (t & 1) * AKV;
        __half* vs_ = ks_ + 64*ASW;
        const __half* kg = qkv + ((size_t)(b*SEQ + t*64))*E3 + EMB + h*HD;
        const __half* vg = kg + EMB;
        #pragma unroll
        for (int i = 0; i < 4; i++) {
            int gi = tid + i*128;
            int row = gi >> 3, c8 = (gi & 7) * 8;
            cp16(&ks_[row*ASW + c8], kg + (size_t)row*E3 + c8);
            cp16(&vs_[row*VSW + c8], vg + (size_t)row*E3 + c8);
        }
    };

    kv_issue(0); CP_COMMIT();

    // stage Q (pre-scaled by GEMM1 epilogue) - plain 16B copies
    {
        const __half* qg = qkv + ((size_t)(b*SEQ + q0))*E3 + h*HD;
        const __half* qrow = qg + (size_t)tid*E3;
        #pragma unroll
        for (int gr = 0; gr < 9; gr++)
            *(uint4*)&q_s[tid*ASW + gr*8] = *(const uint4*)(qrow + gr*8);
    }

    // ones columns for both v stage buffers (cols 64..71: {1,0,...})
    if (tid < 64) {
        uint4 w;
        w.x = packh2(1.0f, 0.0f);
        w.y = 0u; w.z = 0u; w.w = 0u;
        #pragma unroll
        for (int sbuf = 0; sbuf < 2; sbuf++) {
            __half* vs = sma + 128*ASW + sbuf*AKV + 64*ASW;
            *(uint4*)&vs[tid*VSW + 64] = w;
        }
    }
    __syncthreads();

    // hoist loop-invariant Q fragments into registers
    const uint32_t qwb = (uint32_t)(wr*ASW*2);
    uint32_t aqr[2][4][4];
    #pragma unroll
    for (int ks = 0; ks < 4; ks++) {
        ldsm_x4(aqr[0][ks], q_u + qwb + (uint32_t)(ks*16*2)            + ax_off);
        ldsm_x4(aqr[1][ks], q_u + qwb + (uint32_t)((16*ASW + ks*16)*2) + ax_off);
    }

    float oacc[2][8][4] = {};
    float oaccS[2][4] = {};            // ones-column sums (col 64 -> c0/c2)

    const int KT = SEQ/64;
    for (int t = 0; t < KT; t++) {
        CP_WAIT(0);
        __syncthreads();
        if (t + 1 < KT) { kv_issue(t + 1); CP_COMMIT(); }

        const uint32_t k_u = smem_u32(sma + 128*ASW + (t & 1) * AKV);
        const uint32_t v_u = k_u + 64*ASW*2;
        const int kt = t * 64;

        // ---- S = Q @ K^T : K fragments shared across both m-tiles ----
        float s[2][8][4] = {};
        #pragma unroll
        for (int ks = 0; ks < 4; ks++) {
            #pragma unroll
            for (int p = 0; p < 4; p++) {
                uint32_t bk[4];
                ldsm_x4(bk, k_u + (uint32_t)(((p*16)*ASW + ks*16) * 2) + bx_off);
                #pragma unroll
                for (int mt = 0; mt < 2; mt++) {
                    mma_f16(s[mt][2*p],     aqr[mt][ks], bk[0], bk[1]);
                    mma_f16(s[mt][2*p + 1], aqr[mt][ks], bk[2], bk[3]);
                }
            }
        }

        // ---- relative-position bias: flat fast path / exact gather ----
        float cb = 0.f;
        if (kt <= hiThresh)      cb = bias_hi;
        else if (kt >= loThresh) cb = bias_lo;
        else {
            #pragma unroll
            for (int mt = 0; mt < 2; mt++) {
                int qr = q0 + wr + mt*16 + g;
                #pragma unroll
                for (int nt = 0; nt < 8; nt++) {
                    int kcol = kt + nt*8 + 2*t4;
                    int idx0 = qr - kcol + (SEQ - 1);
                    s[mt][nt][0] += __ldg(&g_bias[idx0]);
                    s[mt][nt][1] += __ldg(&g_bias[idx0 - 1]);
                    s[mt][nt][2] += __ldg(&g_bias[idx0 + 8]);
                    s[mt][nt][3] += __ldg(&g_bias[idx0 + 7]);
                }
            }
        }

        // ---- fixed-shift softmax: p = exp2(s + cb - C) ----
        const __half2 sh = __float2half2_rn(SOFT_C - cb);
        uint32_t pp[2][2][8];
        #pragma unroll
        for (int mt = 0; mt < 2; mt++) {
            #pragma unroll
            for (int nt = 0; nt < 8; nt++) {
                __half2 h0; { uint32_t u = packh2(s[mt][nt][0], s[mt][nt][1]); h0 = *(__half2*)&u; }
                __half2 h1; { uint32_t u = packh2(s[mt][nt][2], s[mt][nt][3]); h1 = *(__half2*)&u; }
                __half2 e0 = h2exp2(__hsub2(h0, sh));
                __half2 e1 = h2exp2(__hsub2(h1, sh));
                pp[mt][0][nt] = *(uint32_t*)&e0;
                pp[mt][1][nt] = *(uint32_t*)&e1;
            }
        }

        // ---- O += P @ V ; ones-column mma accumulates row sums ----
        #pragma unroll
        for (int ks = 0; ks < 4; ks++) {
            uint32_t ap[2][4];
            #pragma unroll
            for (int mt = 0; mt < 2; mt++) {
                ap[mt][0] = pp[mt][0][2*ks];
                ap[mt][1] = pp[mt][1][2*ks];
                ap[mt][2] = pp[mt][0][2*ks + 1];
                ap[mt][3] = pp[mt][1][2*ks + 1];
            }
            #pragma unroll
            for (int p = 0; p < 4; p++) {
                uint32_t bv[4];
                ldsm_x4_t(bv, v_u + (uint32_t)(((ks*16)*VSW + p*16) * 2) + av_off);
                #pragma unroll
                for (int mt = 0; mt < 2; mt++) {
                    mma_f16(oacc[mt][2*p],     ap[mt], bv[0], bv[1]);
                    mma_f16(oacc[mt][2*p + 1], ap[mt], bv[2], bv[3]);
                }
            }
            // sums: cols 64-71 (col 64 == 1.0)
            uint32_t bs2[2];
            ldsm_x2_t(bs2, v_u + (uint32_t)(((ks*16)*VSW + 64) * 2) + av_off);
            #pragma unroll
            for (int mt = 0; mt < 2; mt++)
                mma_f16(oaccS[mt], ap[mt], bs2[0], bs2[1]);
        }
    }

    // epilogue: broadcast row sums (held in t4==0 quads), normalize, store
    #pragma unroll
    for (int mt = 0; mt < 2; mt++) {
        float l0 = __shfl_sync(0xffffffffu, oaccS[mt][0], lane & 0x1c);
        float l1 = __shfl_sync(0xffffffffu, oaccS[mt][2], lane & 0x1c);
        float inv0 = 1.0f / l0;
        float inv1 = 1.0f / l1;
        __half* og = ctx + ((size_t)(b*SEQ + q0 + wr + mt*16 + g))*EMB + h*HD;
        #pragma unroll
        for (int nt = 0; nt < 8; nt++) {
            int d = nt*8 + 2*t4;
            *(__half2*)(og + d) = __floats2half2_rn(oacc[mt][nt][0]*inv0, oacc[mt][nt][1]*inv0);
            *(__half2*)(og + (size_t)8*EMB + d) = __floats2half2_rn(oacc[mt][nt][2]*inv1, oacc[mt][nt][3]*inv1);
        }
    }
}

// ---------------- launch ----------------
extern "C" void kernel_launch(void* const* d_in, const int* in_sizes, int n_in,
                              void* d_out, int out_size)
{
    const float* x   = (const float*)d_in[0];
    const float* w1  = (const float*)d_in[1];
    const float* b1  = (const float*)d_in[2];
    const float* w2  = (const float*)d_in[3];
    const float* b2  = (const float*)d_in[4];
    const float* rb  = (const float*)d_in[5];
    const int*   md  = (const int*)d_in[6];
    float* out = (float*)d_out;

    __half *qkv, *ctxp, *xh, *w1h, *w2h;
    cudaGetSymbolAddress((void**)&qkv,  g_qkv);
    cudaGetSymbolAddress((void**)&ctxp, g_ctx);
    cudaGetSymbolAddress((void**)&xh,   g_xh);
    cudaGetSymbolAddress((void**)&w1h,  g_w1h);
    cudaGetSymbolAddress((void**)&w2h,  g_w2h);

    const int gemm_smem = 2 * GSTGH * (int)sizeof(__half);              // 73728 B
    const int attn_smem = (128*ASW + 2*AKV) * (int)sizeof(__half);      // 57344 B
    cudaFuncSetAttribute(gemm_f16_kernel,
                         cudaFuncAttributeMaxDynamicSharedMemorySize, gemm_smem);
    cudaFuncSetAttribute(attn_f16_kernel,
                         cudaFuncAttributeMaxDynamicSharedMemorySize, attn_smem);

    int n4x  = MROWS*EMB/4, n4w1 = E3*EMB/4, n4w2 = EMB*EMB/4;
    int n4all = n4x + n4w1 + n4w2;
    prep_all_kernel<<<1 + (n4all + 255)/256, 256>>>(rb, md,
                                                    x, xh, n4x,
                                                    w1, w1h, n4w1,
                                                    w2, w2h, n4w2);

    dim3 g1(E3/128, MROWS/128);       // (24, 64)
    gemm_f16_kernel<<<g1, 128, gemm_smem>>>(xh, w1h, b1, qkv, MROWS, E3, EMB,
                                            1, EMB, QSCALE);

    dim3 ga(SEQ/128, BATCH*NH);       // (16, 64)
    attn_f16_kernel<<<ga, 128, attn_smem>>>(qkv, ctxp);

    dim3 g2(EMB/128, MROWS/128);      // (8, 64)
    gemm_f16_kernel<<<g2, 128, gemm_smem>>>(ctxp, w2h, b2, out, MROWS, EMB, EMB,
                                            0, 0, 1.0f);
}

// round 17
// speedup vs baseline: 1.2128x; 1.1799x over previous
#include <cuda_runtime.h>
#include <cuda_fp16.h>
#include <cstdint>

#define BATCH 4
#define SEQ   2048
#define EMB   1024
#define NH    16
#define HD    64
#define E3    (3*EMB)
#define MROWS (BATCH*SEQ)

#define QSCALE 0.180336879f               // 0.125 * log2(e)

// tile geometry (halfs)
#define TW   72                           // K/Q/x/w tile row stride
#define VW   80                           // V tile row stride (ones at col 64)
#define GT   (128*TW)                     // 9216 halfs / 18432 B gemm-input tile
#define KTH  (64*TW)                      // 4608 halfs K tile
#define VTH  (64*VW)                      // 5120 halfs V tile

// ---------------- scratch (tiled, static device allocations) ---------------
__device__ __half g_xt [(size_t)64*16*GT];        // x   [mblk][kblk][128][72]
__device__ __half g_w1t[(size_t)24*16*GT];        // w1  [nblk][kblk][128][72]
__device__ __half g_w2t[(size_t)8 *16*GT];        // w2  [nblk][kblk][128][72]
__device__ __half g_qt [(size_t)64*16*GT];        // Q   [bh][qblk][128][72] (pre-scaled)
__device__ __half g_kt [(size_t)64*32*KTH];       // K   [bh][kblk][64][72]
__device__ __half g_vt [(size_t)64*32*VTH];       // V   [bh][kblk][64][80], col64=1
__device__ __half g_ct [(size_t)64*16*GT];        // ctx [mblk][kblk][128][72]
__device__ float  g_bias[2*SEQ - 1];
__device__ int    g_maxd;

// ---------------- helpers ----------------
__device__ __forceinline__ void mma_f16(float c[4], const uint32_t a[4],
                                        uint32_t b0, uint32_t b1) {
    asm volatile(
        "mma.sync.aligned.m16n8k16.row.col.f32.f16.f16.f32 "
        "{%0,%1,%2,%3}, {%4,%5,%6,%7}, {%8,%9}, {%0,%1,%2,%3};"
        : "+f"(c[0]), "+f"(c[1]), "+f"(c[2]), "+f"(c[3])
        : "r"(a[0]), "r"(a[1]), "r"(a[2]), "r"(a[3]), "r"(b0), "r"(b1));
}

__device__ __forceinline__ void ldsm_x4(uint32_t* r, uint32_t addr) {
    asm volatile("ldmatrix.sync.aligned.m8n8.x4.shared.b16 {%0,%1,%2,%3}, [%4];"
                 : "=r"(r[0]), "=r"(r[1]), "=r"(r[2]), "=r"(r[3]) : "r"(addr));
}
__device__ __forceinline__ void ldsm_x4_t(uint32_t* r, uint32_t addr) {
    asm volatile("ldmatrix.sync.aligned.m8n8.x4.trans.shared.b16 {%0,%1,%2,%3}, [%4];"
                 : "=r"(r[0]), "=r"(r[1]), "=r"(r[2]), "=r"(r[3]) : "r"(addr));
}
__device__ __forceinline__ void ldsm_x2_t(uint32_t* r, uint32_t addr) {
    asm volatile("ldmatrix.sync.aligned.m8n8.x2.trans.shared.b16 {%0,%1}, [%2];"
                 : "=r"(r[0]), "=r"(r[1]) : "r"(addr));
}

__device__ __forceinline__ uint32_t smem_u32(const void* p) {
    return (uint32_t)__cvta_generic_to_shared(p);
}
__device__ __forceinline__ uint32_t packh2(float a, float b) {
    __half2 h = __floats2half2_rn(a, b);
    return *(uint32_t*)&h;
}

// mbarrier + 1D bulk-copy (baseline sm_90 PTX; NOT tcgen05/TMA-tensor)
#define MBAR_INIT(addr, cnt) \
    asm volatile("mbarrier.init.shared.b64 [%0], %1;" :: "r"(addr), "r"(cnt) : "memory")
#define MBAR_EXPECT(addr, bytes) \
    asm volatile("mbarrier.arrive.expect_tx.shared.b64 _, [%0], %1;" :: "r"(addr), "r"(bytes) : "memory")
#define MBAR_WAIT(addr, phase) do {                                           \
    asm volatile("{\n\t.reg .pred P1;\n\t"                                    \
        "WAIT_LOOP_%=:\n\t"                                                   \
        "mbarrier.try_wait.parity.acquire.cta.shared::cta.b64 P1, [%0], %1, 0x989680;\n\t" \
        "@P1 bra.uni WAIT_DONE_%=;\n\t"                                       \
        "bra.uni WAIT_LOOP_%=;\n\t"                                           \
        "WAIT_DONE_%=:\n\t}"                                                  \
        :: "r"(addr), "r"(phase) : "memory");                                 \
} while (0)
__device__ __forceinline__ void bulk_g2s(uint32_t dst, const void* src,
                                         uint32_t bytes, uint32_t mbar) {
    asm volatile("cp.async.bulk.shared::cta.global.mbarrier::complete_tx::bytes "
                 "[%0], [%1], %2, [%3];"
                 :: "r"(dst), "l"(src), "r"(bytes), "r"(mbar) : "memory");
}

// ---------------- unified prep -------------------------------------------
// block 0: bias table. others: tiled fp32->fp16 conversion of x/w1/w2 and
// V ones-column fill.
__global__ void prep_all_kernel(const float* __restrict__ rel_bias,
                                const int* __restrict__ p_maxd,
                                const float* __restrict__ xs,
                                const float* __restrict__ w1s,
                                const float* __restrict__ w2s)
{
    if (blockIdx.x == 0) {
        __shared__ float b1d[512];
        int M = *p_maxd;
        if (threadIdx.x == 0) g_maxd = M;
        int n = 2*M + 1;
        if (n > 512) n = 512;
        for (int r = threadIdx.x; r < n; r += blockDim.x) {
            float s = 0.f;
            #pragma unroll
            for (int h = 0; h < NH; h++) s += rel_bias[r*NH + h];
            b1d[r] = s * (1.0f / NH) * 1.44269504f;
        }
        __syncthreads();
        for (int t = threadIdx.x; t < 2*SEQ - 1; t += blockDim.x) {
            int d = t - (SEQ - 1);
            d = max(-M, min(M, d));
            g_bias[t] = b1d[d + M];
        }
        return;
    }
    const int n0 = MROWS*EMB/4;     // x float4s
    const int n1 = E3*EMB/4;        // w1
    const int n2 = EMB*EMB/4;       // w2
    const int n3 = 64*32*64*2;      // V ones rows * 2 uint4
    int i = (blockIdx.x - 1) * blockDim.x + threadIdx.x;

    if (i < n0 + n1 + n2) {
        const float* src; __half* dst; int K = 1024;
        if (i < n0)            { src = xs;  dst = g_xt; }
        else if (i < n0 + n1)  { src = w1s; dst = g_w1t; i -= n0; }
        else                   { src = w2s; dst = g_w2t; i -= n0 + n1; }
        int e = i * 4;
        int r = e >> 10, c = e & 1023;
        float4 v = *(const float4*)(src + (size_t)r*K + c);
        __half2 h0 = __floats2half2_rn(v.x, v.y);
        __half2 h1 = __floats2half2_rn(v.z, v.w);
        uint2 u;
        u.x = *(uint32_t*)&h0;
        u.y = *(uint32_t*)&h1;
        size_t off = ((size_t)((r >> 7)*16 + (c >> 6)))*GT + (size_t)(r & 127)*TW + (c & 63);
        *(uint2*)(dst + off) = u;
    } else {
        int j = i - (n0 + n1 + n2);
        if (j < n3) {
            int row = j >> 1, part = j & 1;
            uint4 w;
            w.x = part ? 0u : packh2(1.0f, 0.0f);
            w.y = 0u; w.z = 0u; w.w = 0u;
            *(uint4*)(g_vt + (size_t)row*VW + 64 + part*8) = w;
        }
    }
}

// ---------------- FP16 TC GEMM (bulk-copy pipeline) ------------------------
// Block 128x128x64, 128 thr (4 warps), warp tile 64x64. A,W pre-tiled.
// outMode 1: split-scatter into Q/K/V tile buffers (gemm1, N=3072).
// outMode 0: fp32 row-major output (gemm2).
__global__ void __launch_bounds__(128, 3) gemm_f16_kernel(
    const __half* __restrict__ A, const __half* __restrict__ W,
    const float* __restrict__ bias, float* __restrict__ Cout,
    int M, int N, int K, int outMode)
{
    extern __shared__ __half smh[];
    const uint32_t sb = smem_u32(smh);
    // smem: [0:32)B barriers, then 2 stages x (A 18432B + B 18432B)
    __half* stg = smh + 16;

    const int tid  = threadIdx.x;
    const int lane = tid & 31;
    const int warp = tid >> 5;
    const int g    = lane >> 2;
    const int t4   = lane & 3;
    const int wm   = (warp & 1) * 64;
    const int wn   = (warp >> 1) * 64;
    const int m0   = blockIdx.y * 128;
    const int n0   = blockIdx.x * 128;
    const int KT   = K >> 6;

    const int sel = lane >> 3, sub = lane & 7;
    const uint32_t ax_off = (uint32_t)(((((sel & 1)*8 + sub)*TW) + (sel >> 1)*8) * 2);
    const uint32_t bx_off = (uint32_t)(((((sel >> 1)*8 + sub)*TW) + (sel & 1)*8) * 2);

    float acc[4][8][4] = {};

    if (tid == 0) {
        MBAR_INIT(sb, 1);
        MBAR_INIT(sb + 8, 1);
    }
    __syncthreads();
    if (tid == 0) {
        #pragma unroll
        for (int p = 0; p < 2; p++) {
            uint32_t bar = sb + p*8;
            uint32_t d = sb + 32 + p*2*GT*2;
            MBAR_EXPECT(bar, 4*GT);
            bulk_g2s(d,          A + ((size_t)blockIdx.y*KT + p)*GT, 2*GT, bar);
            bulk_g2s(d + 2*GT,   W + ((size_t)blockIdx.x*KT + p)*GT, 2*GT, bar);
        }
    }

    for (int it = 0; it < KT; it++) {
        MBAR_WAIT(sb + (it & 1)*8, (uint32_t)((it >> 1) & 1));

        const uint32_t as_u = sb + 32 + (it & 1)*2*GT*2;
        const uint32_t bs_u = as_u + 2*GT;

        #pragma unroll
        for (int ks = 0; ks < 4; ks++) {
            uint32_t af[4][4], bf[4][4];
            #pragma unroll
            for (int mt = 0; mt < 4; mt++)
                ldsm_x4(af[mt], as_u + (uint32_t)((((wm + mt*16)*TW) + ks*16) * 2) + ax_off);
            #pragma unroll
            for (int p = 0; p < 4; p++)
                ldsm_x4(bf[p], bs_u + (uint32_t)((((wn + p*16)*TW) + ks*16) * 2) + bx_off);
            #pragma unroll
            for (int mt = 0; mt < 4; mt++)
                #pragma unroll
                for (int nt = 0; nt < 8; nt++)
                    mma_f16(acc[mt][nt], af[mt],
                            bf[nt >> 1][(nt & 1)*2], bf[nt >> 1][(nt & 1)*2 + 1]);
        }
        __syncthreads();
        if (it + 2 < KT && tid == 0) {
            uint32_t bar = sb + (it & 1)*8;
            uint32_t d = sb + 32 + (it & 1)*2*GT*2;
            MBAR_EXPECT(bar, 4*GT);
            bulk_g2s(d,        A + ((size_t)blockIdx.y*KT + it + 2)*GT, 2*GT, bar);
            bulk_g2s(d + 2*GT, W + ((size_t)blockIdx.x*KT + it + 2)*GT, 2*GT, bar);
        }
    }

    #pragma unroll
    for (int mt = 0; mt < 4; mt++) {
        int m = m0 + wm + mt*16 + g;
        #pragma unroll
        for (int nt = 0; nt < 8; nt++) {
            int n = n0 + wn + nt*8 + 2*t4;
            float2 bv = *(const float2*)(bias + n);
            float o00 = acc[mt][nt][0] + bv.x, o01 = acc[mt][nt][1] + bv.y;
            float o10 = acc[mt][nt][2] + bv.x, o11 = acc[mt][nt][3] + bv.y;
            if (outMode == 0) {
                *(float2*)(Cout + (size_t)m*N + n)       = make_float2(o00, o01);
                *(float2*)(Cout + (size_t)(m + 8)*N + n) = make_float2(o10, o11);
            } else {
                // scatter into Q/K/V tile buffers
                #pragma unroll
                for (int rr = 0; rr < 2; rr++) {
                    int r = m + rr*8;
                    float a0 = rr ? o10 : o00, a1 = rr ? o11 : o01;
                    int b_ = r >> 11, s = r & 2047;
                    int c = n & 63;
                    __half* dst;
                    if (n < EMB) {
                        int h = n >> 6;
                        a0 *= QSCALE; a1 *= QSCALE;
                        dst = g_qt + ((size_t)((b_*16 + h)*16 + (s >> 7)))*GT
                                   + (size_t)(s & 127)*TW + c;
                    } else if (n < 2*EMB) {
                        int h = (n - EMB) >> 6;
                        dst = g_kt + ((size_t)((b_*16 + h)*32 + (s >> 6)))*KTH
                                   + (size_t)(s & 63)*TW + c;
                    } else {
                        int h = (n - 2*EMB) >> 6;
                        dst = g_vt + ((size_t)((b_*16 + h)*32 + (s >> 6)))*VTH
                                   + (size_t)(s & 63)*VW + c;
                    }
                    *(__half2*)dst = __floats2half2_rn(a0, a1);
                }
            }
        }
    }
}

// ---------------- FP16 TC flash attention (bulk-copy pipeline) -------------
// Grid (SEQ/128, BATCH*NH), 128 threads (4 warps), warp = 32 q-rows.
// Q/K/V staged via cp.async.bulk from tile buffers; ones column lives in
// gmem V tiles. Shift-invariant softmax; row sums via ones-column mma.
#define SOFT_C 4.0f
#define AKV (KTH + VTH)            // halfs per kv stage (9728)
__global__ void __launch_bounds__(128, 2) attn_f16_kernel(__half* __restrict__ dummy)
{
    extern __shared__ __half sma[];
    const uint32_t sb = smem_u32(sma);
    // smem halfs: [0:16) bars (bar0, bar1, barq), q at 16, stages at 16+GT

    const int tid  = threadIdx.x;
    const int lane = tid & 31;
    const int warp = tid >> 5;
    const int g    = lane >> 2;
    const int t4   = lane & 3;
    const int bh = blockIdx.y;
    const int q0 = blockIdx.x * 128;
    const int wr = warp * 32;

    const int sel = lane >> 3, sub = lane & 7;
    const uint32_t ax_off = (uint32_t)(((((sel & 1)*8 + sub)*TW) + (sel >> 1)*8) * 2);
    const uint32_t bx_off = (uint32_t)(((((sel >> 1)*8 + sub)*TW) + (sel & 1)*8) * 2);
    const uint32_t av_off = (uint32_t)(((((sel & 1)*8 + sub)*VW) + (sel >> 1)*8) * 2);
    const uint32_t q_u = sb + 32;

    const int Mrd = g_maxd;
    const float bias_hi = g_bias[2*SEQ - 2];
    const float bias_lo = g_bias[0];
    const int hiThresh = q0 - 63 - Mrd;
    const int loThresh = q0 + 127 + Mrd;

    if (tid == 0) {
        MBAR_INIT(sb, 1);
        MBAR_INIT(sb + 8, 1);
        MBAR_INIT(sb + 16, 1);
    }
    __syncthreads();
    if (tid == 0) {
        MBAR_EXPECT(sb + 16, 2*GT);
        bulk_g2s(q_u, g_qt + ((size_t)bh*16 + blockIdx.x)*GT, 2*GT, sb + 16);
        #pragma unroll
        for (int p = 0; p < 2; p++) {
            uint32_t bar = sb + p*8;
            uint32_t d = sb + 32 + 2*GT + p*2*AKV;
            MBAR_EXPECT(bar, 2*AKV);
            bulk_g2s(d,           g_kt + ((size_t)bh*32 + p)*KTH, 2*KTH, bar);
            bulk_g2s(d + 2*KTH,   g_vt + ((size_t)bh*32 + p)*VTH, 2*VTH, bar);
        }
    }

    // wait Q, hoist loop-invariant Q fragments
    MBAR_WAIT(sb + 16, 0u);
    const uint32_t qwb = (uint32_t)(wr*TW*2);
    uint32_t aqr[2][4][4];
    #pragma unroll
    for (int ks = 0; ks < 4; ks++) {
        ldsm_x4(aqr[0][ks], q_u + qwb + (uint32_t)(ks*16*2)           + ax_off);
        ldsm_x4(aqr[1][ks], q_u + qwb + (uint32_t)((16*TW + ks*16)*2) + ax_off);
    }

    float oacc[2][8][4] = {};
    float oaccS[2][4] = {};

    const int KT = SEQ/64;
    for (int t = 0; t < KT; t++) {
        MBAR_WAIT(sb + (t & 1)*8, (uint32_t)((t >> 1) & 1));

        const uint32_t k_u = sb + 32 + 2*GT + (t & 1)*2*AKV;
        const uint32_t v_u = k_u + 2*KTH;
        const int kt = t * 64;

        // ---- S = Q @ K^T ----
        float s[2][8][4] = {};
        #pragma unroll
        for (int ks = 0; ks < 4; ks++) {
            #pragma unroll
            for (int p = 0; p < 4; p++) {
                uint32_t bk[4];
                ldsm_x4(bk, k_u + (uint32_t)(((p*16)*TW + ks*16) * 2) + bx_off);
                #pragma unroll
                for (int mt = 0; mt < 2; mt++) {
                    mma_f16(s[mt][2*p],     aqr[mt][ks], bk[0], bk[1]);
                    mma_f16(s[mt][2*p + 1], aqr[mt][ks], bk[2], bk[3]);
                }
            }
        }

        // ---- relative-position bias ----
        float cb = 0.f;
        if (kt <= hiThresh)      cb = bias_hi;
        else if (kt >= loThresh) cb = bias_lo;
        else {
            #pragma unroll
            for (int mt = 0; mt < 2; mt++) {
                int qr = q0 + wr + mt*16 + g;
                #pragma unroll
                for (int nt = 0; nt < 8; nt++) {
                    int kcol = kt + nt*8 + 2*t4;
                    int idx0 = qr - kcol + (SEQ - 1);
                    s[mt][nt][0] += __ldg(&g_bias[idx0]);
                    s[mt][nt][1] += __ldg(&g_bias[idx0 - 1]);
                    s[mt][nt][2] += __ldg(&g_bias[idx0 + 8]);
                    s[mt][nt][3] += __ldg(&g_bias[idx0 + 7]);
                }
            }
        }

        // ---- fixed-shift softmax ----
        const __half2 sh = __float2half2_rn(SOFT_C - cb);
        uint32_t pp[2][2][8];
        #pragma unroll
        for (int mt = 0; mt < 2; mt++) {
            #pragma unroll
            for (int nt = 0; nt < 8; nt++) {
                __half2 h0; { uint32_t u = packh2(s[mt][nt][0], s[mt][nt][1]); h0 = *(__half2*)&u; }
                __half2 h1; { uint32_t u = packh2(s[mt][nt][2], s[mt][nt][3]); h1 = *(__half2*)&u; }
                __half2 e0 = h2exp2(__hsub2(h0, sh));
                __half2 e1 = h2exp2(__hsub2(h1, sh));
                pp[mt][0][nt] = *(uint32_t*)&e0;
                pp[mt][1][nt] = *(uint32_t*)&e1;
            }
        }

        // ---- O += P @ V ; ones-column mma accumulates row sums ----
        #pragma unroll
        for (int ks = 0; ks < 4; ks++) {
            uint32_t ap[2][4];
            #pragma unroll
            for (int mt = 0; mt < 2; mt++) {
                ap[mt][0] = pp[mt][0][2*ks];
                ap[mt][1] = pp[mt][1][2*ks];
                ap[mt][2] = pp[mt][0][2*ks + 1];
                ap[mt][3] = pp[mt][1][2*ks + 1];
            }
            #pragma unroll
            for (int p = 0; p < 4; p++) {
                uint32_t bv[4];
                ldsm_x4_t(bv, v_u + (uint32_t)(((ks*16)*VW + p*16) * 2) + av_off);
                #pragma unroll
                for (int mt = 0; mt < 2; mt++) {
                    mma_f16(oacc[mt][2*p],     ap[mt], bv[0], bv[1]);
                    mma_f16(oacc[mt][2*p + 1], ap[mt], bv[2], bv[3]);
                }
            }
            uint32_t bs2[2];
            ldsm_x2_t(bs2, v_u + (uint32_t)(((ks*16)*VW + 64) * 2) + av_off);
            #pragma unroll
            for (int mt = 0; mt < 2; mt++)
                mma_f16(oaccS[mt], ap[mt], bs2[0], bs2[1]);
        }

        __syncthreads();
        if (t + 2 < KT && tid == 0) {
            uint32_t bar = sb + (t & 1)*8;
            uint32_t d = sb + 32 + 2*GT + (t & 1)*2*AKV;
            MBAR_EXPECT(bar, 2*AKV);
            bulk_g2s(d,         g_kt + ((size_t)bh*32 + t + 2)*KTH, 2*KTH, bar);
            bulk_g2s(d + 2*KTH, g_vt + ((size_t)bh*32 + t + 2)*VTH, 2*VTH, bar);
        }
    }

    // epilogue: broadcast row sums, normalize, store tiled ctx
    const int mblkBase = ((bh >> 4)*SEQ + q0) >> 7;   // b*16 + qblk
    #pragma unroll
    for (int mt = 0; mt < 2; mt++) {
        float l0 = __shfl_sync(0xffffffffu, oaccS[mt][0], lane & 0x1c);
        float l1 = __shfl_sync(0xffffffffu, oaccS[mt][2], lane & 0x1c);
        float inv0 = 1.0f / l0;
        float inv1 = 1.0f / l1;
        int rl = wr + mt*16 + g;
        __half* og = g_ct + ((size_t)(mblkBase*16 + (bh & 15)))*GT + (size_t)rl*TW;
        #pragma unroll
        for (int nt = 0; nt < 8; nt++) {
            int d = nt*8 + 2*t4;
            *(__half2*)(og + d)        = __floats2half2_rn(oacc[mt][nt][0]*inv0, oacc[mt][nt][1]*inv0);
            *(__half2*)(og + 8*TW + d) = __floats2half2_rn(oacc[mt][nt][2]*inv1, oacc[mt][nt][3]*inv1);
        }
    }
    (void)dummy;
}

// ---------------- launch ----------------
extern "C" void kernel_launch(void* const* d_in, const int* in_sizes, int n_in,
                              void* d_out, int out_size)
{
    const float* x   = (const float*)d_in[0];
    const float* w1  = (const float*)d_in[1];
    const float* b1  = (const float*)d_in[2];
    const float* w2  = (const float*)d_in[3];
    const float* b2  = (const float*)d_in[4];
    const float* rb  = (const float*)d_in[5];
    const int*   md  = (const int*)d_in[6];
    float* out = (float*)d_out;

    __half *xt, *w1t, *w2t, *ct;
    cudaGetSymbolAddress((void**)&xt,  g_xt);
    cudaGetSymbolAddress((void**)&w1t, g_w1t);
    cudaGetSymbolAddress((void**)&w2t, g_w2t);
    cudaGetSymbolAddress((void**)&ct,  g_ct);

    const int gemm_smem = 32 + 2*2*GT*2;                 // 73760 B
    const int attn_smem = 32 + 2*GT + 2*2*AKV;           // 57376 B
    cudaFuncSetAttribute(gemm_f16_kernel,
                         cudaFuncAttributeMaxDynamicSharedMemorySize, gemm_smem);
    cudaFuncSetAttribute(attn_f16_kernel,
                         cudaFuncAttributeMaxDynamicSharedMemorySize, attn_smem);

    int nconv = MROWS*EMB/4 + E3*EMB/4 + EMB*EMB/4 + 64*32*64*2;
    prep_all_kernel<<<1 + (nconv + 255)/256, 256>>>(rb, md, x, w1, w2);

    dim3 g1(E3/128, MROWS/128);       // (24, 64)
    gemm_f16_kernel<<<g1, 128, gemm_smem>>>(xt, w1t, b1, nullptr, MROWS, E3, EMB, 1);

    dim3 ga(SEQ/128, BATCH*NH);       // (16, 64)
    attn_f16_kernel<<<ga, 128, attn_smem>>>(nullptr);

    dim3 g2(EMB/128, MROWS/128);      // (8, 64)
    gemm_f16_kernel<<<g2, 128, gemm_smem>>>(ct, w2t, b2, out, MROWS, EMB, EMB, 0);
}